// round 1
// baseline (speedup 1.0000x reference)
#include <cuda_runtime.h>
#include <cuda_bf16.h>
#include <math.h>

// Scratch (device globals — no allocation allowed).
#define MAXN 16384
__device__ float g_v[MAXN];
__device__ int   g_comp[MAXN];
__device__ int   g_compMin[MAXN];
__device__ float g_breakVals[MAXN];
__device__ int   g_breakCount;

// ---------------------------------------------------------------------------
// K1: per-pixel mean of late timesteps; writes grid tail of out; inits scratch.
// ---------------------------------------------------------------------------
__global__ void k1_mean_init(const float* __restrict__ spikes,
                             const int* __restrict__ cls_start,
                             float* __restrict__ out, int N, int T)
{
    int n = blockIdx.x * blockDim.x + threadIdx.x;
    if (n >= N) return;
    int cs = cls_start[0];
    int start = cs - 1;
    if (start < 0) start = 0;
    if (start > T - 1) start = T - 1;
    int cnt = T - start;
    float s = 0.0f;
    #pragma unroll 4
    for (int t = start; t < T; ++t)
        s += spikes[(size_t)t * N + n];
    float m = s / (float)cnt;
    g_v[n] = m;
    out[(size_t)N * N + n] = m;           // mean_spike_grid
    g_compMin[n] = 0x7fffffff;
    if (n == 0) g_breakCount = 0;
}

// ---------------------------------------------------------------------------
// K2: warp-per-node break detection (early exit) + grid-stride zero fill of
//     the N*N mask region. Break detection is tiny; fill is HBM-bound.
// ---------------------------------------------------------------------------
__global__ void __launch_bounds__(1024)
k2_breaks_and_fill(float* __restrict__ out, int N)
{
    extern __shared__ float sv[];
    int tid = threadIdx.x;
    for (int i = tid; i < N; i += blockDim.x) sv[i] = g_v[i];
    __syncthreads();

    int warpId = tid >> 5;
    int lane   = tid & 31;
    int node   = blockIdx.x * 32 + warpId;   // gridDim.x = ceil(N/32)

    if (node < N) {
        float vi = sv[node];
        bool found = false, anyGreater = false;
        for (int base = 0; base < N; base += 32) {
            int j = base + lane;
            float vj = (j < N) ? sv[j] : vi;
            bool g = vj > vi;
            // EXACT reference predicate: similarity >= 0.6
            bool w = g && (1.0f - (vj - vi) >= 0.6f);
            unsigned mW = __ballot_sync(0xffffffffu, w);
            unsigned mG = __ballot_sync(0xffffffffu, g);
            anyGreater |= (mG != 0u);
            if (mW) { found = true; break; }   // uniform across warp
        }
        if (!found && anyGreater && lane == 0) {
            int slot = atomicAdd(&g_breakCount, 1);
            if (slot < MAXN) g_breakVals[slot] = vi;
        }
    }

    // Zero-fill the mask region (N*N floats, N*N % 4 == 0 for N=9216).
    size_t total4 = ((size_t)N * (size_t)N) >> 2;
    float4 z = make_float4(0.f, 0.f, 0.f, 0.f);
    float4* o4 = reinterpret_cast<float4*>(out);
    size_t stride = (size_t)gridDim.x * blockDim.x;
    for (size_t p = (size_t)blockIdx.x * blockDim.x + tid; p < total4; p += stride)
        o4[p] = z;
    // Handle any tail floats (none for N divisible by 2, but be safe).
    size_t tail_start = total4 << 2;
    size_t totalf = (size_t)N * (size_t)N;
    for (size_t p = tail_start + (size_t)blockIdx.x * blockDim.x + tid; p < totalf; p += stride)
        out[p] = 0.0f;
}

// ---------------------------------------------------------------------------
// K3: component id = #distinct break values < v[n]; track min index per comp.
// ---------------------------------------------------------------------------
__global__ void k3_comp(int N)
{
    int n = blockIdx.x * blockDim.x + threadIdx.x;
    if (n >= N) return;
    int K = g_breakCount;
    if (K > MAXN) K = MAXN;
    float vn = g_v[n];
    int comp = 0;
    for (int k = 0; k < K; ++k) {
        float b = g_breakVals[k];
        if (b < vn) {
            bool firstOcc = true;
            for (int j = 0; j < k; ++j)
                if (g_breakVals[j] == b) { firstOcc = false; break; }
            if (firstOcc) comp++;
        }
    }
    g_comp[n] = comp;
    atomicMin(&g_compMin[comp], n);
}

// ---------------------------------------------------------------------------
// K4: scatter ones: masks[label[n], n] = 1
// ---------------------------------------------------------------------------
__global__ void k4_scatter(float* __restrict__ out, int N)
{
    int n = blockIdx.x * blockDim.x + threadIdx.x;
    if (n >= N) return;
    int label = g_compMin[g_comp[n]];
    out[(size_t)label * N + n] = 1.0f;
}

// ---------------------------------------------------------------------------
extern "C" void kernel_launch(void* const* d_in, const int* in_sizes, int n_in,
                              void* d_out, int out_size)
{
    const float* spikes = (const float*)d_in[0];
    const int*   cstart = (const int*)d_in[1];
    float* out = (float*)d_out;

    // Solve N from out_size = N*N + N (host-side, no device reads needed).
    size_t S = (size_t)out_size;
    int N = (int)((sqrt(4.0 * (double)S + 1.0) - 1.0) * 0.5);
    while ((size_t)N * N + N > S) N--;
    while ((size_t)(N + 1) * (N + 1) + (N + 1) <= S) N++;
    int T = in_sizes[0] / N;   // batch = 1

    int tb = 256;
    int nb = (N + tb - 1) / tb;

    k1_mean_init<<<nb, tb>>>(spikes, cstart, out, N, T);

    int gridB = (N + 31) / 32;                 // warp-per-node
    size_t smem = (size_t)N * sizeof(float);
    k2_breaks_and_fill<<<gridB, 1024, smem>>>(out, N);

    k3_comp<<<nb, tb>>>(N);
    k4_scatter<<<nb, tb>>>(out, N);
}

// round 2
// speedup vs baseline: 1.0629x; 1.0629x over previous
#include <cuda_runtime.h>
#include <cuda_bf16.h>
#include <math.h>

// Scratch (device globals — no allocation allowed).
#define MAXN 16384
__device__ float g_v[MAXN];
__device__ float g_breakVals[MAXN];
__device__ int   g_breakCount;
__device__ unsigned int g_ticket;

// ---------------------------------------------------------------------------
// K1: per-pixel mean of late timesteps; writes grid tail of out; resets scratch.
// ---------------------------------------------------------------------------
__global__ void k1_mean_init(const float* __restrict__ spikes,
                             const int* __restrict__ cls_start,
                             float* __restrict__ out, int N, int T)
{
    int n = blockIdx.x * blockDim.x + threadIdx.x;
    if (n >= N) return;
    int cs = cls_start[0];
    int start = cs - 1;
    if (start < 0) start = 0;
    if (start > T - 1) start = T - 1;
    int cnt = T - start;
    float s = 0.0f;
    #pragma unroll 4
    for (int t = start; t < T; ++t)
        s += spikes[(size_t)t * N + n];
    float m = s / (float)cnt;
    g_v[n] = m;
    out[(size_t)N * N + n] = m;           // mean_spike_grid tail
    if (n == 0) { g_breakCount = 0; g_ticket = 0u; }
}

// ---------------------------------------------------------------------------
// K2: fused — break detection + 340MB zero fill + (last block) labels+scatter.
//
// Interval-graph insight: adj(i,j) = (1 - |vi-vj| >= 0.6). Components are
// maximal sorted-value runs separated by gaps where no strictly-greater value
// within threshold exists. A node is a "break" if it is its run's max value
// and a strictly greater value exists. comp(n) = #distinct break values < v_n.
// label(n) = min pixel index in comp(n).
// ---------------------------------------------------------------------------
__global__ void __launch_bounds__(1024)
k2_fused(float* __restrict__ out, int N)
{
    extern __shared__ float smem_raw[];
    float* sv   = smem_raw;                       // [N] pixel values
    int*   sMin = (int*)(smem_raw + N);           // [N] per-component min index

    int tid = threadIdx.x;
    for (int i = tid; i < N; i += blockDim.x) sv[i] = g_v[i];
    __syncthreads();

    // ---- Phase 1: break detection (warp-per-node, early exit) ----
    int warpId = tid >> 5;
    int lane   = tid & 31;
    int node   = blockIdx.x * 32 + warpId;
    if (node < N) {
        float vi = sv[node];
        bool found = false, anyGreater = false;
        for (int base = 0; base < N; base += 32) {
            int j = base + lane;
            float vj = (j < N) ? sv[j] : vi;
            bool g = vj > vi;
            // EXACT reference predicate: similarity >= 0.6
            bool w = g && (1.0f - (vj - vi) >= 0.6f);
            unsigned mW = __ballot_sync(0xffffffffu, w);
            unsigned mG = __ballot_sync(0xffffffffu, g);
            anyGreater |= (mG != 0u);
            if (mW) { found = true; break; }     // uniform across warp
        }
        if (!found && anyGreater && lane == 0) {
            int slot = atomicAdd(&g_breakCount, 1);
            if (slot < MAXN) g_breakVals[slot] = vi;
        }
    }

    // ---- Phase 2: zero-fill the N*N mask region (streaming float4 stores) ----
    size_t total4 = ((size_t)N * (size_t)N) >> 2;   // N*N % 4 == 0 for N=9216
    float4 z = make_float4(0.f, 0.f, 0.f, 0.f);
    float4* o4 = reinterpret_cast<float4*>(out);
    size_t stride = (size_t)gridDim.x * blockDim.x;
    for (size_t p = (size_t)blockIdx.x * blockDim.x + tid; p < total4; p += stride)
        __stcs(&o4[p], z);

    // ---- Phase 3: last finished block computes labels + scatters ones ----
    __threadfence();
    __shared__ int isLast;
    if (tid == 0) {
        unsigned t = atomicAdd(&g_ticket, 1u);
        isLast = (t == gridDim.x - 1u) ? 1 : 0;
    }
    __syncthreads();
    if (!isLast) return;

    int K = atomicAdd(&g_breakCount, 0);   // acquire-ish read of final count
    if (K > MAXN) K = MAXN;

    for (int i = tid; i < N; i += blockDim.x) sMin[i] = 0x7fffffff;
    __syncthreads();

    // comp(n) = #distinct break values < v_n; track per-comp min index.
    for (int n = tid; n < N; n += blockDim.x) {
        float vn = sv[n];
        int comp = 0;
        for (int k = 0; k < K; ++k) {
            float b = g_breakVals[k];
            if (b < vn) {
                bool firstOcc = true;
                for (int j = 0; j < k; ++j)
                    if (g_breakVals[j] == b) { firstOcc = false; break; }
                if (firstOcc) comp++;
            }
        }
        atomicMin_block(&sMin[comp], n);
    }
    __syncthreads();

    // Scatter: masks[label(n), n] = 1 (all other blocks finished their fill).
    for (int n = tid; n < N; n += blockDim.x) {
        float vn = sv[n];
        int comp = 0;
        for (int k = 0; k < K; ++k) {
            float b = g_breakVals[k];
            if (b < vn) {
                bool firstOcc = true;
                for (int j = 0; j < k; ++j)
                    if (g_breakVals[j] == b) { firstOcc = false; break; }
                if (firstOcc) comp++;
            }
        }
        int label = sMin[comp];
        out[(size_t)label * N + n] = 1.0f;
    }
}

// ---------------------------------------------------------------------------
extern "C" void kernel_launch(void* const* d_in, const int* in_sizes, int n_in,
                              void* d_out, int out_size)
{
    const float* spikes = (const float*)d_in[0];
    const int*   cstart = (const int*)d_in[1];
    float* out = (float*)d_out;

    // Solve N from out_size = N*N + N.
    size_t S = (size_t)out_size;
    int N = (int)((sqrt(4.0 * (double)S + 1.0) - 1.0) * 0.5);
    while ((size_t)N * N + N > S) N--;
    while ((size_t)(N + 1) * (N + 1) + (N + 1) <= S) N++;
    int T = in_sizes[0] / N;   // batch = 1

    int tb = 256;
    int nb = (N + tb - 1) / tb;
    k1_mean_init<<<nb, tb>>>(spikes, cstart, out, N, T);

    // 296 blocks = 2 per SM on 148 SMs; covers warp-per-node (296*32 >= N).
    int gridB = 296;
    int minB = (N + 31) / 32;
    if (gridB < minB) gridB = minB;
    size_t smem = (size_t)N * sizeof(float) + (size_t)N * sizeof(int);
    cudaFuncSetAttribute(k2_fused, cudaFuncAttributeMaxDynamicSharedMemorySize,
                         (int)smem);
    k2_fused<<<gridB, 1024, smem>>>(out, N);
}

// round 3
// speedup vs baseline: 1.3276x; 1.2490x over previous
#include <cuda_runtime.h>
#include <math.h>

#define MAXBREAK 16384
#define NB 4096

__device__ float    g_breakVals[MAXBREAK];
__device__ int      g_compMin[MAXBREAK];
__device__ unsigned g_ticketB;   // monotone across graph replays; snapshot-based

__device__ __forceinline__ unsigned encodeKey(float f) {
    unsigned u = __float_as_uint(f);
    return (u & 0x80000000u) ? ~u : (u | 0x80000000u);
}
__device__ __forceinline__ float decodeKey(unsigned k) {
    unsigned u = (k & 0x80000000u) ? (k & 0x7fffffffu) : ~k;
    return __uint_as_float(u);
}

// ---------------------------------------------------------------------------
// One fused kernel.
//   Block 0            : means -> grid tail -> exact break detection (bins)
//                        -> row 0 of masks -> (K>0 only) wait + scatter.
//   Blocks 1..gridDim-1: pure streaming zero-fill of mask rows [1, N).
//
// Interval-graph fact: adj(i,j) = (1.0f - |vi-vj| >= 0.6f) is a monotone
// threshold predicate, so components = maximal sorted-value runs; breaks occur
// exactly between consecutive sorted values failing the predicate. With bin
// width w such that P(2w) holds, breaks can only occur between consecutive
// OCCUPIED bins, tested exactly on (max of lower bin, min of upper bin).
// comp(n) = #breaks with breakVal < v_n; label(n) = min index in comp.
// ---------------------------------------------------------------------------
__global__ void __launch_bounds__(1024)
mega_kernel(const float* __restrict__ spikes, const int* __restrict__ cstart,
            float* __restrict__ out, int N, int T)
{
    extern __shared__ unsigned smem_u[];
    int tid = threadIdx.x;

    // ======================= FILLER BLOCKS ================================
    if (blockIdx.x != 0) {
        size_t start4 = ((size_t)N) >> 2;                 // skip row 0
        size_t total4 = ((size_t)N * (size_t)N) >> 2;     // N*N % 4 == 0
        float4 z = make_float4(0.f, 0.f, 0.f, 0.f);
        float4* o4 = reinterpret_cast<float4*>(out);
        size_t stride = (size_t)(gridDim.x - 1) * blockDim.x;
        for (size_t p = start4 + (size_t)(blockIdx.x - 1) * blockDim.x + tid;
             p < total4; p += stride)
            __stcs(&o4[p], z);
        __threadfence();
        __syncthreads();
        if (tid == 0) atomicAdd(&g_ticketB, 1u);
        return;
    }

    // ======================= ANALYSIS BLOCK (block 0) =====================
    unsigned baseTicket = atomicAdd(&g_ticketB, 0u);  // snapshot before any
                                                      // filler can finish

    float*    v      = reinterpret_cast<float*>(smem_u);   // [N]
    unsigned* binMin = smem_u + N;                          // [NB]
    unsigned* binMax = binMin + NB;                         // [NB]
    __shared__ unsigned sKeyMin, sKeyMax, sFirstBin;
    __shared__ int sK;

    if (tid == 0) { sKeyMin = 0xFFFFFFFFu; sKeyMax = 0u; sFirstBin = NB; sK = 0; }
    for (int b = tid; b < NB; b += 1024) { binMin[b] = 0xFFFFFFFFu; binMax[b] = 0u; }
    __syncthreads();

    // ---- means (coalesced over n), grid tail, key min/max ----
    int cs = cstart[0];
    int st = cs - 1;
    if (st < 0) st = 0;
    if (st > T - 1) st = T - 1;
    int cnt = T - st;
    unsigned lmin = 0xFFFFFFFFu, lmax = 0u;
    for (int n = tid; n < N; n += 1024) {
        float s = 0.0f;
        #pragma unroll 8
        for (int t = st; t < T; ++t)
            s += spikes[(size_t)t * N + n];
        float m = s / (float)cnt;
        v[n] = m;
        out[(size_t)N * N + n] = m;                 // mean_spike_grid tail
        unsigned k = encodeKey(m);
        lmin = min(lmin, k);
        lmax = max(lmax, k);
    }
    atomicMin_block(&sKeyMin, lmin);
    atomicMax_block(&sKeyMax, lmax);
    __syncthreads();

    float vmin = decodeKey(sKeyMin);
    float vmax = decodeKey(sKeyMax);
    float range = vmax - vmin;
    // bin path valid iff within-bin spread (<= ~2w conservatively) passes P
    bool binOK = (range > 0.0f) &&
                 (1.0f - (range * (2.0f / (float)NB)) >= 0.6f);

    int K = 0;
    if (binOK) {
        float inv = (float)NB / range;
        for (int n = tid; n < N; n += 1024) {
            float x = v[n];
            int b = (int)((x - vmin) * inv);
            if (b >= NB) b = NB - 1;
            if (b < 0) b = 0;
            unsigned k = encodeKey(x);
            atomicMin_block(&binMin[b], k);
            atomicMax_block(&binMax[b], k);
        }
        __syncthreads();
        for (int b = tid; b < NB; b += 1024)
            if (binMin[b] != 0xFFFFFFFFu) atomicMin_block(&sFirstBin, (unsigned)b);
        __syncthreads();
        // breaks: exact predicate on (max of prev occupied bin, min of this bin)
        for (int b = tid; b < NB; b += 1024) {
            if (binMin[b] != 0xFFFFFFFFu && b > (int)sFirstBin) {
                int p = b - 1;
                while (binMin[p] == 0xFFFFFFFFu) --p;
                float lo = decodeKey(binMax[p]);
                float hi = decodeKey(binMin[b]);
                float d = hi - lo;                      // exact pair distance
                if (!(1.0f - d >= 0.6f)) {              // EXACT ref predicate
                    int slot = atomicAdd_block(&sK, 1);
                    if (slot < MAXBREAK) g_breakVals[slot] = lo;
                }
            }
        }
        __syncthreads();
        K = sK;
    } else if (range > 0.0f) {
        // exact warp-scan fallback (pathological ranges only)
        int warpId = tid >> 5, lane = tid & 31;
        for (int node = warpId; node < N; node += 32) {
            float vi = v[node];
            bool found = false, anyG = false;
            for (int base = 0; base < N; base += 32) {
                int j = base + lane;
                float vj = (j < N) ? v[j] : vi;
                bool g = vj > vi;
                bool wq = g && (1.0f - (vj - vi) >= 0.6f);
                unsigned mW = __ballot_sync(0xffffffffu, wq);
                unsigned mG = __ballot_sync(0xffffffffu, g);
                anyG |= (mG != 0u);
                if (mW) { found = true; break; }
            }
            if (!found && anyG && lane == 0) {
                int slot = atomicAdd_block(&sK, 1);
                if (slot < MAXBREAK) g_breakVals[slot] = vi;
            }
        }
        __syncthreads();
        K = sK;
    }
    if (K > MAXBREAK) K = MAXBREAK;

    // comp(x) = #distinct break values < x (dedup only matters for fallback)
    auto compOf = [&](float x) {
        int c = 0;
        for (int k = 0; k < K; ++k) {
            float b = g_breakVals[k];
            if (b < x) {
                bool first = true;
                for (int j = 0; j < k; ++j)
                    if (g_breakVals[j] == b) { first = false; break; }
                if (first) c++;
            }
        }
        return c;
    };

    // ---- row 0: masks[0, n] = (label(n) == 0) = (comp(n) == comp(0)) ----
    int comp0 = compOf(v[0]);
    for (int n = tid; n < N; n += 1024)
        out[n] = (compOf(v[n]) == comp0) ? 1.0f : 0.0f;

    if (K == 0) return;   // single component: done, no post-fill sync needed

    // ---- general case: per-comp min index, then scatter after fill ----
    for (int c = tid; c <= K && c < MAXBREAK; c += 1024)
        g_compMin[c] = 0x7fffffff;
    __syncthreads();
    for (int n = tid; n < N; n += 1024)
        atomicMin(&g_compMin[compOf(v[n])], n);
    __syncthreads();

    if (tid == 0) {
        unsigned need = gridDim.x - 1u;
        while (atomicAdd(&g_ticketB, 0u) - baseTicket < need)
            __nanosleep(128);
    }
    __syncthreads();
    __threadfence();

    for (int n = tid; n < N; n += 1024) {
        int c = compOf(v[n]);
        int m = atomicAdd(&g_compMin[c], 0);
        if (m != 0)                      // row 0 already written above
            out[(size_t)m * N + n] = 1.0f;
    }
}

// ---------------------------------------------------------------------------
extern "C" void kernel_launch(void* const* d_in, const int* in_sizes, int n_in,
                              void* d_out, int out_size)
{
    const float* spikes = (const float*)d_in[0];
    const int*   cstart = (const int*)d_in[1];
    float* out = (float*)d_out;

    // Solve N from out_size = N*N + N.
    size_t S = (size_t)out_size;
    int N = (int)((sqrt(4.0 * (double)S + 1.0) - 1.0) * 0.5);
    while ((size_t)N * N + N > S) N--;
    while ((size_t)(N + 1) * (N + 1) + (N + 1) <= S) N++;
    int T = in_sizes[0] / N;   // batch = 1

    int grid = 296;                       // 2 blocks / SM on 148 SMs
    size_t smem = (size_t)N * sizeof(float) + 2u * NB * sizeof(unsigned);
    static int attrSet = 0;
    (void)attrSet;
    cudaFuncSetAttribute(mega_kernel,
                         cudaFuncAttributeMaxDynamicSharedMemorySize,
                         (int)smem);
    mega_kernel<<<grid, 1024, smem>>>(spikes, cstart, out, N, T);
}